// round 6
// baseline (speedup 1.0000x reference)
#include <cuda_runtime.h>
#include <math.h>

// Problem constants
#define SS_ 512   // sequence
#define UU_ 128   // users (batch)
#define HH_ 512   // hidden
#define H3_ 1536  // 3*H
#define VV_ 2048  // vocab
#define F_DAY 86400.0f
#define F_LT  0.1f
#define F_LS  1.0f

#define GRU_BLOCKS 128
#define GRU_THREADS 128

// ---------------- scratch (device globals; allocation is banned) -------------
__device__ float g_gi[(size_t)SS_ * UU_ * H3_];   // [S][U][3H] input-side gates
__device__ float g_out[(size_t)SS_ * UU_ * HH_];  // [S][U][H]  GRU outputs
__device__ float g_outw[(size_t)SS_ * UU_ * HH_]; // [S][U][H]  weighted outputs
__device__ float g_w[(size_t)UU_ * SS_ * SS_];    // [U][S][S]  causal weights
__device__ float g_sumw[UU_ * SS_];               // [U][S]
__device__ float g_WihT[HH_ * H3_];               // [K=H][N=3H]
__device__ float g_WhhT[HH_ * H3_];
__device__ float g_fcwT[HH_ * VV_];               // [K=H][N=V]
__device__ float g_tT[UU_ * SS_];                 // t transposed [U][S]
__device__ float g_sx[UU_ * SS_];
__device__ float g_sy[UU_ * SS_];
__device__ float g_ghp[2 * UU_ * H3_];            // split-K partials of gh
__device__ unsigned g_cnt;                        // global barrier counter

// ---------------- prep: transposes + barrier reset ---------------------------
__global__ void prep_kernel(const float* __restrict__ Wih,
                            const float* __restrict__ Whh,
                            const float* __restrict__ fcw,
                            const float* __restrict__ t,
                            const float* __restrict__ s)
{
    int idx = blockIdx.x * blockDim.x + threadIdx.x;
    if (idx == 0) g_cnt = 0;                      // reset software barrier each replay
    if (idx < HH_ * H3_) {
        int k = idx / H3_, n = idx % H3_;
        g_WihT[idx] = Wih[(size_t)n * HH_ + k];
        g_WhhT[idx] = Whh[(size_t)n * HH_ + k];
    }
    if (idx < HH_ * VV_) {
        int k = idx / VV_, v = idx % VV_;
        g_fcwT[idx] = fcw[(size_t)v * HH_ + k];
    }
    if (idx < UU_ * SS_) {
        int u = idx / SS_, i = idx % SS_;
        g_tT[idx] = t[(size_t)i * UU_ + u];
        g_sx[idx] = s[((size_t)i * UU_ + u) * 2 + 0];
        g_sy[idx] = s[((size_t)i * UU_ + u) * 2 + 1];
    }
}

// ---------------- generic 128x128x8 SGEMM (fp32) -----------------------------
// MODE 0: gi  = gather(emb, x) @ WihT + b_ih        C=g_gi
// MODE 1: y   = g_outw @ fcwT + fc_b                C=Cparam (d_out)
// MODE 2: per-user attention GEMM with 1/sumw scale C=g_outw (z = user)
template<int MODE>
__global__ __launch_bounds__(256)
void sgemm128(const int* __restrict__ gidx,
              const float* __restrict__ gtbl,
              const float* __restrict__ bias,
              float* __restrict__ Cparam,
              int Ktot)
{
    const int n0 = blockIdx.x * 128;
    const int m0 = blockIdx.y * 128;

    const float* A;
    const float* B;
    float* C;
    int lda, ldb, ldc;
    if (MODE == 0) { A = nullptr;  B = g_WihT; C = g_gi;    lda = 0;   ldb = H3_;      ldc = H3_; }
    else if (MODE == 1) { A = g_outw; B = g_fcwT; C = Cparam; lda = HH_; ldb = VV_;     ldc = VV_; }
    else {
        int u = blockIdx.z;
        A = g_w   + (size_t)u * SS_ * SS_;
        B = g_out + (size_t)u * HH_;
        C = g_outw + (size_t)u * HH_;
        lda = SS_; ldb = UU_ * HH_; ldc = UU_ * HH_;
    }
    int kmax = Ktot;
    if (MODE == 2) { int lim = m0 + 128; kmax = (Ktot < lim) ? Ktot : lim; }

    __shared__ float  As[8][128];
    __shared__ float4 Bs[8][32];

    const int tid = threadIdx.x;
    const int tx = tid & 15;   // n micro-tile
    const int ty = tid >> 4;   // m micro-tile

    // A tile load mapping: 128 rows x 8 k, one float4 per thread
    const int am = tid >> 1;
    const int ak = (tid & 1) * 4;
    const float* aRow;
    if (MODE == 0) {
        int row = gidx[m0 + am];
        aRow = gtbl + (size_t)row * HH_ + ak;
    } else {
        aRow = A + (size_t)(m0 + am) * lda + ak;
    }
    // B tile load mapping: 8 rows x 32 float4, one float4 per thread
    const int br = tid >> 5;
    const int bc = tid & 31;
    const float* bPtr = B + (size_t)br * ldb + n0 + bc * 4;

    float acc[8][8];
#pragma unroll
    for (int i = 0; i < 8; i++)
#pragma unroll
        for (int j = 0; j < 8; j++) acc[i][j] = 0.f;

    for (int k0 = 0; k0 < kmax; k0 += 8) {
        float4 va = *(const float4*)(aRow + k0);
        As[ak + 0][am] = va.x; As[ak + 1][am] = va.y;
        As[ak + 2][am] = va.z; As[ak + 3][am] = va.w;
        Bs[br][bc] = *(const float4*)(bPtr + (size_t)k0 * ldb);
        __syncthreads();
#pragma unroll
        for (int k = 0; k < 8; k++) {
            float4 a0 = *(const float4*)&As[k][ty * 8];
            float4 a1 = *(const float4*)&As[k][ty * 8 + 4];
            float4 b0 = Bs[k][tx * 2];
            float4 b1 = Bs[k][tx * 2 + 1];
            float a[8] = {a0.x, a0.y, a0.z, a0.w, a1.x, a1.y, a1.z, a1.w};
            float b[8] = {b0.x, b0.y, b0.z, b0.w, b1.x, b1.y, b1.z, b1.w};
#pragma unroll
            for (int i = 0; i < 8; i++)
#pragma unroll
                for (int j = 0; j < 8; j++)
                    acc[i][j] = fmaf(a[i], b[j], acc[i][j]);
        }
        __syncthreads();
    }

    float bv[8];
    if (MODE != 2) {
#pragma unroll
        for (int j = 0; j < 8; j++) bv[j] = bias[n0 + tx * 8 + j];
    }
#pragma unroll
    for (int i = 0; i < 8; i++) {
        int m = m0 + ty * 8 + i;
        float* cRow = C + (size_t)m * ldc + n0 + tx * 8;
        float4 v0, v1;
        if (MODE == 2) {
            float sc = 1.f / g_sumw[blockIdx.z * SS_ + m];
            v0 = make_float4(acc[i][0] * sc, acc[i][1] * sc, acc[i][2] * sc, acc[i][3] * sc);
            v1 = make_float4(acc[i][4] * sc, acc[i][5] * sc, acc[i][6] * sc, acc[i][7] * sc);
        } else {
            v0 = make_float4(acc[i][0] + bv[0], acc[i][1] + bv[1], acc[i][2] + bv[2], acc[i][3] + bv[3]);
            v1 = make_float4(acc[i][4] + bv[4], acc[i][5] + bv[5], acc[i][6] + bv[6], acc[i][7] + bv[7]);
        }
        *(float4*)cRow       = v0;
        *(float4*)(cRow + 4) = v1;
    }
}

// ---------------- persistent GRU: all 512 steps in ONE kernel ----------------
// Grid 128 blocks x 128 threads, all co-resident; global software barrier.
// Per step: phase A = split-K(2) x 4 u-tiles(32) x 16 n-tiles(96) gh-GEMM;
//           phase B = reduce partials + gates + h update.
__device__ __forceinline__ void grid_barrier(unsigned& target)
{
    __syncthreads();
    if (threadIdx.x == 0) {
        __threadfence();
        atomicAdd(&g_cnt, 1u);
        target += GRU_BLOCKS;
        while (*(volatile unsigned*)&g_cnt < target) { }
        __threadfence();
    }
    __syncthreads();
}

__global__ __launch_bounds__(GRU_THREADS)
void gru_persistent(const float* __restrict__ h0,
                    const float* __restrict__ bhh)
{
    const int bz = blockIdx.x;
    const int kc = bz & 1;            // K split (0/1)
    const int u0 = ((bz >> 1) & 3) * 32;
    const int n0 = (bz >> 3) * 96;    // 16 n-tiles of 96
    const int kbase = kc * 256;

    const int tid = threadIdx.x;
    const int ty  = tid >> 4;         // 8 u-groups of 4
    const int txn = tid & 15;         // 16 n-groups of 6

    __shared__ float As[16][32];      // [k][u]
    __shared__ float Bs[16][96];      // [k][n]

    const int au  = tid >> 2;         // 0..31
    const int ak4 = (tid & 3) * 4;    // 0,4,8,12

    unsigned target = 0;

    for (int st = 0; st < SS_; st++) {
        const float* hp = (st == 0) ? h0 : (g_out + (size_t)(st - 1) * UU_ * HH_);

        // ---- phase A: partial gh = hp[u0:+32, kbase:+256] @ WhhT[., n0:+96]
        float acc[4][6];
#pragma unroll
        for (int i = 0; i < 4; i++)
#pragma unroll
            for (int j = 0; j < 6; j++) acc[i][j] = 0.f;

        const float* aBase = hp + (size_t)(u0 + au) * HH_ + kbase + ak4;

        for (int kk = 0; kk < 256; kk += 16) {
            float4 va = *(const float4*)(aBase + kk);
            As[ak4 + 0][au] = va.x; As[ak4 + 1][au] = va.y;
            As[ak4 + 2][au] = va.z; As[ak4 + 3][au] = va.w;
#pragma unroll
            for (int it = 0; it < 3; it++) {
                int idx = tid + it * 128;
                int r = idx / 24, c = idx % 24;
                *(float4*)&Bs[r][c * 4] =
                    *(const float4*)&g_WhhT[(size_t)(kbase + kk + r) * H3_ + n0 + c * 4];
            }
            __syncthreads();
#pragma unroll
            for (int k = 0; k < 16; k++) {
                float4 a = *(const float4*)&As[k][ty * 4];
                float av[4] = {a.x, a.y, a.z, a.w};
                float bv[6];
#pragma unroll
                for (int j = 0; j < 6; j++) bv[j] = Bs[k][txn * 6 + j];
#pragma unroll
                for (int i = 0; i < 4; i++)
#pragma unroll
                    for (int j = 0; j < 6; j++)
                        acc[i][j] = fmaf(av[i], bv[j], acc[i][j]);
            }
            __syncthreads();
        }
#pragma unroll
        for (int i = 0; i < 4; i++) {
            float* p = &g_ghp[(size_t)(kc * UU_ + u0 + ty * 4 + i) * H3_ + n0 + txn * 6];
#pragma unroll
            for (int j = 0; j < 6; j++) p[j] = acc[i][j];
        }

        grid_barrier(target);

        // ---- phase B: reduce split-K, gates, h update -> g_out[st]
#pragma unroll
        for (int e = 0; e < 4; e++) {
            int idx = e * (GRU_BLOCKS * GRU_THREADS) + bz * GRU_THREADS + tid;  // 0..65535
            int u = idx >> 9;
            int j = idx & 511;
            const float* p0 = &g_ghp[(size_t)u * H3_];
            const float* p1 = &g_ghp[(size_t)(UU_ + u) * H3_];
            float hr = p0[j]        + p1[j]        + bhh[j];
            float hz = p0[512 + j]  + p1[512 + j]  + bhh[512 + j];
            float hn = p0[1024 + j] + p1[1024 + j] + bhh[1024 + j];
            const float* gi = g_gi + ((size_t)st * UU_ + u) * H3_;
            float r = 1.f / (1.f + __expf(-(gi[j] + hr)));
            float z = 1.f / (1.f + __expf(-(gi[512 + j] + hz)));
            float n = tanhf(gi[1024 + j] + r * hn);
            float hprev = hp[(size_t)u * HH_ + j];
            g_out[(size_t)st * UU_ * HH_ + idx] = (1.f - z) * n + z * hprev;
        }

        grid_barrier(target);
    }
}

// ---------------- causal spatiotemporal weight matrix ------------------------
__global__ void wmat_kernel()
{
    const int i = blockIdx.x;
    const int u = blockIdx.y;
    const float ti  = g_tT[u * SS_ + i];
    const float sxi = g_sx[u * SS_ + i];
    const float syi = g_sy[u * SS_ + i];

    float lsum = 0.f;
    for (int j = threadIdx.x; j < SS_; j += 256) {
        float wv = 0.f;
        if (j <= i) {
            float dt = ti - g_tT[u * SS_ + j];
            float dx = sxi - g_sx[u * SS_ + j];
            float dy = syi - g_sy[u * SS_ + j];
            float ds = sqrtf(dx * dx + dy * dy);
            wv = __expf(-dt * (F_LT / F_DAY) - F_LS * ds) + 1e-10f;
        }
        g_w[((size_t)u * SS_ + i) * SS_ + j] = wv;
        lsum += wv;
    }
    __shared__ float red[256];
    red[threadIdx.x] = lsum;
    __syncthreads();
    for (int o = 128; o > 0; o >>= 1) {
        if (threadIdx.x < o) red[threadIdx.x] += red[threadIdx.x + o];
        __syncthreads();
    }
    if (threadIdx.x == 0) g_sumw[u * SS_ + i] = red[0];
}

// copy h_last = out[S-1] to tail of d_out
__global__ void hlast_kernel(float* __restrict__ out)
{
    int i = blockIdx.x * blockDim.x + threadIdx.x;
    if (i < UU_ * HH_)
        out[(size_t)SS_ * UU_ * VV_ + i] = g_out[(size_t)(SS_ - 1) * UU_ * HH_ + i];
}

// ---------------- launcher ---------------------------------------------------
extern "C" void kernel_launch(void* const* d_in, const int* in_sizes, int n_in,
                              void* d_out, int out_size)
{
    const int*   x   = (const int*)d_in[0];
    const float* t   = (const float*)d_in[1];
    const float* s   = (const float*)d_in[2];
    // d_in[3] y_t, d_in[4] y_s, d_in[6] active_user: unused by reference
    const float* h0  = (const float*)d_in[5];
    const float* emb = (const float*)d_in[7];
    const float* Wih = (const float*)d_in[8];
    const float* Whh = (const float*)d_in[9];
    const float* bih = (const float*)d_in[10];
    const float* bhh = (const float*)d_in[11];
    const float* fcw = (const float*)d_in[12];
    const float* fcb = (const float*)d_in[13];
    float* out = (float*)d_out;

    // 1. transposes + barrier reset
    prep_kernel<<<(HH_ * VV_ + 255) / 256, 256>>>(Wih, Whh, fcw, t, s);

    // 2. gi = emb[x] @ W_ih^T + b_ih   (M=S*U=65536, N=1536, K=512)
    sgemm128<0><<<dim3(H3_ / 128, (SS_ * UU_) / 128, 1), 256>>>(x, emb, bih, nullptr, HH_);

    // 3. GRU recurrence: 512 steps inside ONE persistent kernel
    gru_persistent<<<GRU_BLOCKS, GRU_THREADS>>>(h0, bhh);

    // 4. causal spatiotemporal weights + row sums
    wmat_kernel<<<dim3(SS_, UU_), 256>>>();

    // 5. out_w = (w @ out) / sum_w   (per-user 512x512x512, triangular K-limit)
    sgemm128<2><<<dim3(HH_ / 128, SS_ / 128, UU_), 256>>>(nullptr, nullptr, nullptr, nullptr, SS_);

    // 6. y = out_w @ fc_w^T + fc_b   (M=65536, N=2048, K=512) -> d_out
    sgemm128<1><<<dim3(VV_ / 128, (SS_ * UU_) / 128, 1), 256>>>(nullptr, nullptr, fcb, out, HH_);

    // 7. h_last
    hlast_kernel<<<(UU_ * HH_ + 255) / 256, 256>>>(out);
}

// round 7
// speedup vs baseline: 1.2788x; 1.2788x over previous
#include <cuda_runtime.h>
#include <math.h>

// Problem constants
#define SS_ 512   // sequence
#define UU_ 128   // users (batch)
#define HH_ 512   // hidden
#define H3_ 1536  // 3*H
#define VV_ 2048  // vocab
#define F_DAY 86400.0f
#define F_LT  0.1f
#define F_LS  1.0f

#define GRU_BLOCKS 128
#define GRU_THREADS 256

typedef unsigned long long u64t;

// ---------------- packed fp32x2 helpers (Blackwell FFMA2) --------------------
__device__ __forceinline__ u64t pk2(float lo, float hi) {
    u64t r; asm("mov.b64 %0, {%1, %2};" : "=l"(r) : "f"(lo), "f"(hi)); return r;
}
__device__ __forceinline__ void ffma2(u64t& d, u64t a, u64t b) {
    asm("fma.rn.f32x2 %0, %1, %2, %0;" : "+l"(d) : "l"(a), "l"(b));
}
__device__ __forceinline__ float2 upk(u64t v) {
    float2 r; asm("mov.b64 {%0, %1}, %2;" : "=f"(r.x), "=f"(r.y) : "l"(v)); return r;
}

// ---------------- scratch (device globals; allocation is banned) -------------
__device__ float g_gi[(size_t)SS_ * UU_ * H3_];   // [S][U][3H] input-side gates
__device__ float g_out[(size_t)SS_ * UU_ * HH_];  // [S][U][H]  GRU outputs
__device__ float g_outw[(size_t)SS_ * UU_ * HH_]; // [S][U][H]  weighted outputs
__device__ float g_w[(size_t)UU_ * SS_ * SS_];    // [U][S][S]  causal weights
__device__ float g_sumw[UU_ * SS_];               // [U][S]
__device__ float g_WihT[HH_ * H3_];               // [K=H][N=3H]
__device__ float g_WhhT[HH_ * H3_];
__device__ float g_fcwT[HH_ * VV_];               // [K=H][N=V]
__device__ float g_tT[UU_ * SS_];                 // t transposed [U][S]
__device__ float g_sx[UU_ * SS_];
__device__ float g_sy[UU_ * SS_];
__device__ float g_ghp[2 * UU_ * H3_];            // split-K partials of gh
__device__ unsigned g_cnt;                        // global barrier counter

// ---------------- prep: transposes + barrier reset ---------------------------
__global__ void prep_kernel(const float* __restrict__ Wih,
                            const float* __restrict__ Whh,
                            const float* __restrict__ fcw,
                            const float* __restrict__ t,
                            const float* __restrict__ s)
{
    int idx = blockIdx.x * blockDim.x + threadIdx.x;
    if (idx == 0) g_cnt = 0;                      // reset software barrier each replay
    if (idx < HH_ * H3_) {
        int k = idx / H3_, n = idx % H3_;
        g_WihT[idx] = Wih[(size_t)n * HH_ + k];
        g_WhhT[idx] = Whh[(size_t)n * HH_ + k];
    }
    if (idx < HH_ * VV_) {
        int k = idx / VV_, v = idx % VV_;
        g_fcwT[idx] = fcw[(size_t)v * HH_ + k];
    }
    if (idx < UU_ * SS_) {
        int u = idx / SS_, i = idx % SS_;
        g_tT[idx] = t[(size_t)i * UU_ + u];
        g_sx[idx] = s[((size_t)i * UU_ + u) * 2 + 0];
        g_sy[idx] = s[((size_t)i * UU_ + u) * 2 + 1];
    }
}

// ---------------- 128x128x16 double-buffered FFMA2 SGEMM ---------------------
// MODE 0: gi  = gather(emb, x) @ WihT + b_ih        C=g_gi
// MODE 1: y   = g_outw @ fcwT + fc_b                C=Cparam (d_out)
// MODE 2: per-user attention GEMM with 1/sumw scale C=g_outw (z = user)
template<int MODE>
__global__ __launch_bounds__(256, 2)
void sgemm2(const int* __restrict__ gidx,
            const float* __restrict__ gtbl,
            const float* __restrict__ bias,
            float* __restrict__ Cparam,
            int Ktot)
{
    const int n0 = blockIdx.x * 128;
    const int m0 = blockIdx.y * 128;

    const float* A;
    const float* B;
    float* C;
    int lda, ldb, ldc;
    if (MODE == 0)      { A = nullptr;  B = g_WihT; C = g_gi;    lda = 0;   ldb = H3_; ldc = H3_; }
    else if (MODE == 1) { A = g_outw;   B = g_fcwT; C = Cparam;  lda = HH_; ldb = VV_; ldc = VV_; }
    else {
        int u = blockIdx.z;
        A = g_w    + (size_t)u * SS_ * SS_;
        B = g_out  + (size_t)u * HH_;
        C = g_outw + (size_t)u * HH_;
        lda = SS_; ldb = UU_ * HH_; ldc = UU_ * HH_;
    }
    int kmax = Ktot;
    if (MODE == 2) { int lim = m0 + 128; kmax = (Ktot < lim) ? Ktot : lim; }

    __shared__ float As[2][16][128];
    __shared__ float Bs[2][16][128];

    const int tid = threadIdx.x;
    const int tx4 = (tid & 15) * 4;
    const int ty4 = (tid >> 4) * 4;

    // fill mappings
    const int ar  = tid >> 1;          // A row 0..127
    const int akk = (tid & 1) * 8;     // A k base 0 or 8
    const float* aRow;
    if (MODE == 0) {
        int row = gidx[m0 + ar];
        aRow = gtbl + (size_t)row * HH_ + akk;
    } else {
        aRow = A + (size_t)(m0 + ar) * lda + akk;
    }
    const int br  = tid >> 4;          // B row 0..15
    const int bcc = (tid & 15) * 8;    // B col base
    const float* bPtr = B + (size_t)br * ldb + n0 + bcc;

    u64t acc[4][8];
#pragma unroll
    for (int i = 0; i < 4; i++)
#pragma unroll
        for (int j = 0; j < 8; j++) acc[i][j] = 0ULL;

    // prologue: stage 0
    float4 pa0 = *(const float4*)(aRow);
    float4 pa1 = *(const float4*)(aRow + 4);
    float4 pb0 = *(const float4*)(bPtr);
    float4 pb1 = *(const float4*)(bPtr + 4);
    As[0][akk + 0][ar] = pa0.x; As[0][akk + 1][ar] = pa0.y;
    As[0][akk + 2][ar] = pa0.z; As[0][akk + 3][ar] = pa0.w;
    As[0][akk + 4][ar] = pa1.x; As[0][akk + 5][ar] = pa1.y;
    As[0][akk + 6][ar] = pa1.z; As[0][akk + 7][ar] = pa1.w;
    *(float4*)&Bs[0][br][bcc]     = pb0;
    *(float4*)&Bs[0][br][bcc + 4] = pb1;
    __syncthreads();

    const int nk = kmax >> 4;
    int buf = 0;
    for (int kt = 0; kt < nk; kt++) {
        if (kt + 1 < nk) {
            int kn = (kt + 1) << 4;
            pa0 = *(const float4*)(aRow + kn);
            pa1 = *(const float4*)(aRow + kn + 4);
            pb0 = *(const float4*)(bPtr + (size_t)kn * ldb);
            pb1 = *(const float4*)(bPtr + (size_t)kn * ldb + 4);
        }
#pragma unroll
        for (int k = 0; k < 16; k++) {
            float4 a0 = *(const float4*)&As[buf][k][ty4];
            float4 a1 = *(const float4*)&As[buf][k][64 + ty4];
            float4 b0 = *(const float4*)&Bs[buf][k][tx4];
            float4 b1 = *(const float4*)&Bs[buf][k][64 + tx4];
            u64t ap[4];
            ap[0] = pk2(a0.x, a0.y); ap[1] = pk2(a0.z, a0.w);
            ap[2] = pk2(a1.x, a1.y); ap[3] = pk2(a1.z, a1.w);
            u64t bd[8];
            bd[0] = pk2(b0.x, b0.x); bd[1] = pk2(b0.y, b0.y);
            bd[2] = pk2(b0.z, b0.z); bd[3] = pk2(b0.w, b0.w);
            bd[4] = pk2(b1.x, b1.x); bd[5] = pk2(b1.y, b1.y);
            bd[6] = pk2(b1.z, b1.z); bd[7] = pk2(b1.w, b1.w);
#pragma unroll
            for (int i = 0; i < 4; i++)
#pragma unroll
                for (int j = 0; j < 8; j++)
                    ffma2(acc[i][j], ap[i], bd[j]);
        }
        if (kt + 1 < nk) {
            int nb = buf ^ 1;
            As[nb][akk + 0][ar] = pa0.x; As[nb][akk + 1][ar] = pa0.y;
            As[nb][akk + 2][ar] = pa0.z; As[nb][akk + 3][ar] = pa0.w;
            As[nb][akk + 4][ar] = pa1.x; As[nb][akk + 5][ar] = pa1.y;
            As[nb][akk + 6][ar] = pa1.z; As[nb][akk + 7][ar] = pa1.w;
            *(float4*)&Bs[nb][br][bcc]     = pb0;
            *(float4*)&Bs[nb][br][bcc + 4] = pb1;
            __syncthreads();
            buf = nb;
        }
    }

    // epilogue: rows m0 + {0,64} + ty4 + 0..3 (pairs), cols n0 + {0,64} + tx4 + 0..3
    float bv[8];
    if (MODE != 2) {
#pragma unroll
        for (int j = 0; j < 8; j++)
            bv[j] = bias[n0 + ((j < 4) ? (tx4 + j) : (64 + tx4 + j - 4))];
    }
#pragma unroll
    for (int mp = 0; mp < 4; mp++) {
        int r = m0 + ((mp >= 2) ? 64 : 0) + ty4 + (mp & 1) * 2;   // first row of pair
        float2 v[8];
#pragma unroll
        for (int j = 0; j < 8; j++) v[j] = upk(acc[mp][j]);
        float s0 = 0.f, s1 = 0.f;
        if (MODE == 2) {
            s0 = 1.f / g_sumw[blockIdx.z * SS_ + r];
            s1 = 1.f / g_sumw[blockIdx.z * SS_ + r + 1];
        }
        float4 lo0, lo1, hi0, hi1;
        if (MODE == 2) {
            lo0 = make_float4(v[0].x * s0, v[1].x * s0, v[2].x * s0, v[3].x * s0);
            lo1 = make_float4(v[4].x * s0, v[5].x * s0, v[6].x * s0, v[7].x * s0);
            hi0 = make_float4(v[0].y * s1, v[1].y * s1, v[2].y * s1, v[3].y * s1);
            hi1 = make_float4(v[4].y * s1, v[5].y * s1, v[6].y * s1, v[7].y * s1);
        } else {
            lo0 = make_float4(v[0].x + bv[0], v[1].x + bv[1], v[2].x + bv[2], v[3].x + bv[3]);
            lo1 = make_float4(v[4].x + bv[4], v[5].x + bv[5], v[6].x + bv[6], v[7].x + bv[7]);
            hi0 = make_float4(v[0].y + bv[0], v[1].y + bv[1], v[2].y + bv[2], v[3].y + bv[3]);
            hi1 = make_float4(v[4].y + bv[4], v[5].y + bv[5], v[6].y + bv[6], v[7].y + bv[7]);
        }
        float* c0 = C + (size_t)r * ldc + n0;
        float* c1 = C + (size_t)(r + 1) * ldc + n0;
        *(float4*)&c0[tx4]      = lo0;
        *(float4*)&c0[64 + tx4] = lo1;
        *(float4*)&c1[tx4]      = hi0;
        *(float4*)&c1[64 + tx4] = hi1;
    }
}

// ---------------- persistent GRU: all 512 steps in ONE kernel ----------------
// 128 blocks x 256 threads. W_hh slice cached in smem ONCE; h slice staged
// per step as DUPLICATED pairs for FFMA2. Split-K=2 x 4 u-tiles x 16 n-tiles.
__device__ __forceinline__ void grid_barrier(unsigned& target)
{
    __syncthreads();
    if (threadIdx.x == 0) {
        __threadfence();
        atomicAdd(&g_cnt, 1u);
        target += GRU_BLOCKS;
        while (*(volatile unsigned*)&g_cnt < target) { }
        __threadfence();
    }
    __syncthreads();
}

#define ASH_STRIDE 532   // 2*256 dup floats + 20 pad (keeps 8B align, breaks bank patterns)

__global__ __launch_bounds__(GRU_THREADS)
void gru_persistent(const float* __restrict__ h0,
                    const float* __restrict__ bhh)
{
    extern __shared__ float dsm[];
    float* Wsh = dsm;                         // [256][96]
    float* Ash = dsm + 256 * 96;              // [32][ASH_STRIDE] dup pairs

    const int bz = blockIdx.x;
    const int kc = bz & 1;                    // K split (0/1)
    const int u0 = ((bz >> 1) & 3) * 32;
    const int n0 = (bz >> 3) * 96;            // 16 n-tiles of 96
    const int kbase = kc * 256;

    const int tid = threadIdx.x;
    const int ty = tid >> 4;                  // u-group (2 u each)
    const int tx = tid & 15;                  // n-group (6 n each)

    // cache W_hh slice [256 k][96 n] once
    for (int fi = tid; fi < 256 * 24; fi += GRU_THREADS) {
        int k = fi / 24, c = fi % 24;
        *(float4*)&Wsh[k * 96 + c * 4] =
            *(const float4*)&g_WhhT[(size_t)(kbase + k) * H3_ + n0 + c * 4];
    }

    const int fu = tid >> 3;                  // fill: u row 0..31
    const int fj = (tid & 7) * 4;             // fill: k offset within 32-chunk

    unsigned target = 0;

    for (int st = 0; st < SS_; st++) {
        const float* hp = (st == 0) ? h0 : (g_out + (size_t)(st - 1) * UU_ * HH_);

        // stage h slice as duplicated pairs: Ash[u][2k],[2k+1] = hp[u0+u][kbase+k]
        {
            const float* hrow = hp + (size_t)(u0 + fu) * HH_ + kbase;
            float* drow = &Ash[fu * ASH_STRIDE];
#pragma unroll
            for (int i = 0; i < 8; i++) {
                int kb = fj + 32 * i;
                float4 v = *(const float4*)&hrow[kb];
                float* d = &drow[2 * kb];
                *(float2*)&d[0] = make_float2(v.x, v.x);
                *(float2*)&d[2] = make_float2(v.y, v.y);
                *(float2*)&d[4] = make_float2(v.z, v.z);
                *(float2*)&d[6] = make_float2(v.w, v.w);
            }
        }
        __syncthreads();

        // ---- phase A: FFMA2 inner product over 256 k
        u64t acc[2][3];
        acc[0][0] = acc[0][1] = acc[0][2] = 0ULL;
        acc[1][0] = acc[1][1] = acc[1][2] = 0ULL;
        const float* arow0 = &Ash[(ty * 2 + 0) * ASH_STRIDE];
        const float* arow1 = &Ash[(ty * 2 + 1) * ASH_STRIDE];
        const float* bcol  = &Wsh[tx * 6];
#pragma unroll 8
        for (int k = 0; k < 256; k++) {
            u64t a0 = *(const u64t*)&arow0[2 * k];
            u64t a1 = *(const u64t*)&arow1[2 * k];
            const float* bk = bcol + k * 96;
            u64t b0 = *(const u64t*)&bk[0];
            u64t b1 = *(const u64t*)&bk[2];
            u64t b2 = *(const u64t*)&bk[4];
            ffma2(acc[0][0], a0, b0); ffma2(acc[0][1], a0, b1); ffma2(acc[0][2], a0, b2);
            ffma2(acc[1][0], a1, b0); ffma2(acc[1][1], a1, b1); ffma2(acc[1][2], a1, b2);
        }
#pragma unroll
        for (int uu = 0; uu < 2; uu++) {
            float* dst = g_ghp + (size_t)(kc * UU_ + u0 + ty * 2 + uu) * H3_ + n0 + tx * 6;
            float2 w0 = upk(acc[uu][0]);
            float2 w1 = upk(acc[uu][1]);
            float2 w2 = upk(acc[uu][2]);
            *(float2*)&dst[0] = w0;
            *(float2*)&dst[2] = w1;
            *(float2*)&dst[4] = w2;
        }

        grid_barrier(target);

        // ---- phase B: reduce split-K, gates, h update -> g_out[st]
#pragma unroll
        for (int e = 0; e < 2; e++) {
            int idx = e * (GRU_BLOCKS * GRU_THREADS) + bz * GRU_THREADS + tid;  // 0..65535
            int u = idx >> 9;
            int j = idx & 511;
            const float* p0 = g_ghp + (size_t)u * H3_;
            const float* p1 = g_ghp + (size_t)(UU_ + u) * H3_;
            float hr = p0[j]        + p1[j]        + bhh[j];
            float hz = p0[512 + j]  + p1[512 + j]  + bhh[512 + j];
            float hn = p0[1024 + j] + p1[1024 + j] + bhh[1024 + j];
            const float* gi = g_gi + ((size_t)st * UU_ + u) * H3_;
            float r = 1.f / (1.f + __expf(-(gi[j] + hr)));
            float z = 1.f / (1.f + __expf(-(gi[512 + j] + hz)));
            float a = gi[1024 + j] + r * hn;
            float e2 = __expf(2.f * a);
            float n = 1.f - 2.f / (e2 + 1.f);      // tanh, saturation-safe
            float hprev = hp[(size_t)u * HH_ + j];
            g_out[(size_t)st * UU_ * HH_ + idx] = (1.f - z) * n + z * hprev;
        }

        grid_barrier(target);
    }
}

// ---------------- causal spatiotemporal weight matrix ------------------------
__global__ void wmat_kernel()
{
    const int i = blockIdx.x;
    const int u = blockIdx.y;
    const float ti  = g_tT[u * SS_ + i];
    const float sxi = g_sx[u * SS_ + i];
    const float syi = g_sy[u * SS_ + i];

    float lsum = 0.f;
    for (int j = threadIdx.x; j < SS_; j += 256) {
        float wv = 0.f;
        if (j <= i) {
            float dt = ti - g_tT[u * SS_ + j];
            float dx = sxi - g_sx[u * SS_ + j];
            float dy = syi - g_sy[u * SS_ + j];
            float ds = sqrtf(dx * dx + dy * dy);
            wv = __expf(-dt * (F_LT / F_DAY) - F_LS * ds) + 1e-10f;
        }
        g_w[((size_t)u * SS_ + i) * SS_ + j] = wv;
        lsum += wv;
    }
    __shared__ float red[256];
    red[threadIdx.x] = lsum;
    __syncthreads();
    for (int o = 128; o > 0; o >>= 1) {
        if (threadIdx.x < o) red[threadIdx.x] += red[threadIdx.x + o];
        __syncthreads();
    }
    if (threadIdx.x == 0) g_sumw[u * SS_ + i] = red[0];
}

// copy h_last = out[S-1] to tail of d_out
__global__ void hlast_kernel(float* __restrict__ out)
{
    int i = blockIdx.x * blockDim.x + threadIdx.x;
    if (i < UU_ * HH_)
        out[(size_t)SS_ * UU_ * VV_ + i] = g_out[(size_t)(SS_ - 1) * UU_ * HH_ + i];
}

// ---------------- launcher ---------------------------------------------------
extern "C" void kernel_launch(void* const* d_in, const int* in_sizes, int n_in,
                              void* d_out, int out_size)
{
    const int*   x   = (const int*)d_in[0];
    const float* t   = (const float*)d_in[1];
    const float* s   = (const float*)d_in[2];
    // d_in[3] y_t, d_in[4] y_s, d_in[6] active_user: unused by reference
    const float* h0  = (const float*)d_in[5];
    const float* emb = (const float*)d_in[7];
    const float* Wih = (const float*)d_in[8];
    const float* Whh = (const float*)d_in[9];
    const float* bih = (const float*)d_in[10];
    const float* bhh = (const float*)d_in[11];
    const float* fcw = (const float*)d_in[12];
    const float* fcb = (const float*)d_in[13];
    float* out = (float*)d_out;

    static const int GRU_SMEM = (256 * 96 + 32 * ASH_STRIDE) * 4;   // 166400 B
    cudaFuncSetAttribute(gru_persistent,
                         cudaFuncAttributeMaxDynamicSharedMemorySize, GRU_SMEM);

    // 1. transposes + barrier reset
    prep_kernel<<<(HH_ * VV_ + 255) / 256, 256>>>(Wih, Whh, fcw, t, s);

    // 2. gi = emb[x] @ W_ih^T + b_ih   (M=S*U=65536, N=1536, K=512)
    sgemm2<0><<<dim3(H3_ / 128, (SS_ * UU_) / 128, 1), 256>>>(x, emb, bih, nullptr, HH_);

    // 3. GRU recurrence: 512 steps inside ONE persistent kernel
    gru_persistent<<<GRU_BLOCKS, GRU_THREADS, GRU_SMEM>>>(h0, bhh);

    // 4. causal spatiotemporal weights + row sums
    wmat_kernel<<<dim3(SS_, UU_), 256>>>();

    // 5. out_w = (w @ out) / sum_w   (per-user 512x512x512, triangular K-limit)
    sgemm2<2><<<dim3(HH_ / 128, SS_ / 128, UU_), 256>>>(nullptr, nullptr, nullptr, nullptr, SS_);

    // 6. y = out_w @ fc_w^T + fc_b   (M=65536, N=2048, K=512) -> d_out
    sgemm2<1><<<dim3(VV_ / 128, (SS_ * UU_) / 128, 1), 256>>>(nullptr, nullptr, fcb, out, HH_);

    // 7. h_last
    hlast_kernel<<<(UU_ * HH_ + 255) / 256, 256>>>(out);
}

// round 9
// speedup vs baseline: 1.3853x; 1.0833x over previous
#include <cuda_runtime.h>
#include <cuda_bf16.h>
#include <math.h>
#include <stdint.h>

// Problem constants
#define SS_ 512   // sequence
#define UU_ 128   // users (batch)
#define HH_ 512   // hidden
#define H3_ 1536  // 3*H
#define VV_ 2048  // vocab
#define F_DAY 86400.0f
#define F_LT  0.1f
#define F_LS  1.0f

#define GRU_BLOCKS 128
#define GRU_THREADS 256

typedef unsigned long long u64t;

// ---------------- packed fp32x2 helpers (Blackwell FFMA2) --------------------
__device__ __forceinline__ u64t pk2(float lo, float hi) {
    u64t r; asm("mov.b64 %0, {%1, %2};" : "=l"(r) : "f"(lo), "f"(hi)); return r;
}
__device__ __forceinline__ void ffma2(u64t& d, u64t a, u64t b) {
    asm("fma.rn.f32x2 %0, %1, %2, %0;" : "+l"(d) : "l"(a), "l"(b));
}
__device__ __forceinline__ float2 upk(u64t v) {
    float2 r; asm("mov.b64 {%0, %1}, %2;" : "=f"(r.x), "=f"(r.y) : "l"(v)); return r;
}

// ---------------- bf16 mma.sync helpers (standard PTX, works on sm_103) ------
__device__ __forceinline__ uint32_t pack_bf2(float a, float b) {
    __nv_bfloat162 t = __floats2bfloat162_rn(a, b);
    return *reinterpret_cast<uint32_t*>(&t);
}
__device__ __forceinline__ void mma_bf(float* d, const uint32_t* a, uint32_t b0, uint32_t b1) {
    asm volatile(
        "mma.sync.aligned.m16n8k16.row.col.f32.bf16.bf16.f32 "
        "{%0,%1,%2,%3}, {%4,%5,%6,%7}, {%8,%9}, {%0,%1,%2,%3};"
        : "+f"(d[0]), "+f"(d[1]), "+f"(d[2]), "+f"(d[3])
        : "r"(a[0]), "r"(a[1]), "r"(a[2]), "r"(a[3]), "r"(b0), "r"(b1));
}

// ---------------- scratch (device globals; allocation is banned) -------------
__device__ float g_gi[(size_t)SS_ * UU_ * H3_];   // [S][U][3H] input-side gates
__device__ float g_out[(size_t)SS_ * UU_ * HH_];  // [S][U][H]  GRU outputs
__device__ float g_outw[(size_t)SS_ * UU_ * HH_]; // [S][U][H]  weighted outputs
__device__ float g_w[(size_t)UU_ * SS_ * SS_];    // [U][S][S]  causal weights
__device__ float g_sumw[UU_ * SS_];               // [U][S]
__device__ float g_WhhT[HH_ * H3_];               // [K=H][N=3H] for GRU
__device__ float g_tT[UU_ * SS_];                 // t transposed [U][S]
__device__ float g_sx[UU_ * SS_];
__device__ float g_sy[UU_ * SS_];
__device__ float g_ghp[2 * UU_ * H3_];            // split-K partials of gh
__device__ unsigned g_cnt;                        // global barrier counter

// ---------------- prep: W_hh transpose + t/s relayout + barrier reset --------
__global__ void prep_kernel(const float* __restrict__ Whh,
                            const float* __restrict__ t,
                            const float* __restrict__ s)
{
    int idx = blockIdx.x * blockDim.x + threadIdx.x;
    if (idx == 0) g_cnt = 0;                      // reset software barrier each replay
    if (idx < HH_ * H3_) {
        int k = idx / H3_, n = idx % H3_;
        g_WhhT[idx] = Whh[(size_t)n * HH_ + k];
    }
    if (idx < UU_ * SS_) {
        int u = idx / SS_, i = idx % SS_;
        g_tT[idx] = t[(size_t)i * UU_ + u];
        g_sx[idx] = s[((size_t)i * UU_ + u) * 2 + 0];
        g_sy[idx] = s[((size_t)i * UU_ + u) * 2 + 1];
    }
}

// ---------------- split-bf16 tensor-core GEMM (mma.sync m16n8k16) ------------
// D[m][n] = sum_k A[m][k]*B[n][k] + bias[n], as Ah*Bh + Ah*Bl + Al*Bh (fp32 acc)
// Tile 128x128, 8 warps (warp tile 64x32), K chunks of 32, smem stride 40 bf16
// MODE 0: A = emb[x[m]] (gather), B = W_ih [3H][H], C = g_gi
// MODE 1: A = g_outw,             B = fc_w [V][H],  C = d_out
#define TSTR 40   // smem row stride in bf16 (conflict-free frag loads)

// convert 16 contiguous f32 -> 16 bf16 hi + 16 bf16 lo (32B each, uint4 x2)
__device__ __forceinline__ void cvt16(const float* __restrict__ src,
                                      uint16_t* __restrict__ hd,
                                      uint16_t* __restrict__ ld)
{
    float4 v0 = ((const float4*)src)[0];
    float4 v1 = ((const float4*)src)[1];
    float4 v2 = ((const float4*)src)[2];
    float4 v3 = ((const float4*)src)[3];
    float f[16] = {v0.x, v0.y, v0.z, v0.w, v1.x, v1.y, v1.z, v1.w,
                   v2.x, v2.y, v2.z, v2.w, v3.x, v3.y, v3.z, v3.w};
    uint32_t hp[8], lp[8];
#pragma unroll
    for (int i = 0; i < 8; i++) {
        float a = f[2 * i], b = f[2 * i + 1];
        float ha = __bfloat162float(__float2bfloat16_rn(a));
        float hb = __bfloat162float(__float2bfloat16_rn(b));
        hp[i] = pack_bf2(ha, hb);
        lp[i] = pack_bf2(a - ha, b - hb);
    }
    ((uint4*)hd)[0] = make_uint4(hp[0], hp[1], hp[2], hp[3]);
    ((uint4*)hd)[1] = make_uint4(hp[4], hp[5], hp[6], hp[7]);
    ((uint4*)ld)[0] = make_uint4(lp[0], lp[1], lp[2], lp[3]);
    ((uint4*)ld)[1] = make_uint4(lp[4], lp[5], lp[6], lp[7]);
}

template<int MODE>
__global__ __launch_bounds__(256, 2)
void tgemm(const int* __restrict__ gidx,
           const float* __restrict__ AsrcP,
           const float* __restrict__ Bsrc,
           const float* __restrict__ bias,
           float* __restrict__ Cparam)
{
    __shared__ uint16_t sAh[128 * TSTR];
    __shared__ uint16_t sAl[128 * TSTR];
    __shared__ uint16_t sBh[128 * TSTR];
    __shared__ uint16_t sBl[128 * TSTR];

    const int tid = threadIdx.x;
    const int wid = tid >> 5, lid = tid & 31;
    const int g   = lid >> 2, tig = lid & 3;
    const int wm  = wid & 1;        // 2 warp rows  (64 m each)
    const int wn  = wid >> 1;       // 4 warp cols  (32 n each)
    const int n0  = blockIdx.x * 128;
    const int m0  = blockIdx.y * 128;

    float* C = (MODE == 0) ? g_gi : Cparam;
    const int ldc = (MODE == 0) ? H3_ : VV_;

    // fill mapping: thread covers row r, k-half kh (16 floats)
    const int fr = tid >> 1;
    const int kh = (tid & 1) * 16;
    const float* aSrc;
    if (MODE == 0) aSrc = AsrcP + (size_t)gidx[m0 + fr] * HH_ + kh;
    else           aSrc = g_outw + (size_t)(m0 + fr) * HH_ + kh;
    const float* bSrc = Bsrc + (size_t)(n0 + fr) * HH_ + kh;
    uint16_t* ahd = &sAh[fr * TSTR + kh];
    uint16_t* ald = &sAl[fr * TSTR + kh];
    uint16_t* bhd = &sBh[fr * TSTR + kh];
    uint16_t* bld = &sBl[fr * TSTR + kh];

    float acc[4][4][4];
#pragma unroll
    for (int i = 0; i < 4; i++)
#pragma unroll
        for (int j = 0; j < 4; j++)
#pragma unroll
            for (int q = 0; q < 4; q++) acc[i][j][q] = 0.f;

    for (int kb = 0; kb < HH_; kb += 32) {
        __syncthreads();
        cvt16(aSrc + kb, ahd, ald);
        cvt16(bSrc + kb, bhd, bld);
        __syncthreads();
#pragma unroll
        for (int k16 = 0; k16 < 32; k16 += 16) {
            // B fragments for all 4 n-frags (hi + lo)
            uint32_t bh[4][2], bl[4][2];
#pragma unroll
            for (int nf = 0; nf < 4; nf++) {
                int nb = (wn * 32 + nf * 8 + g) * TSTR + k16 + 2 * tig;
                bh[nf][0] = *(const uint32_t*)&sBh[nb];
                bh[nf][1] = *(const uint32_t*)&sBh[nb + 8];
                bl[nf][0] = *(const uint32_t*)&sBl[nb];
                bl[nf][1] = *(const uint32_t*)&sBl[nb + 8];
            }
#pragma unroll
            for (int mf = 0; mf < 4; mf++) {
                int ab = (wm * 64 + mf * 16 + g) * TSTR + k16 + 2 * tig;
                uint32_t ah[4], al[4];
                ah[0] = *(const uint32_t*)&sAh[ab];
                ah[1] = *(const uint32_t*)&sAh[ab + 8 * TSTR];
                ah[2] = *(const uint32_t*)&sAh[ab + 8];
                ah[3] = *(const uint32_t*)&sAh[ab + 8 * TSTR + 8];
                al[0] = *(const uint32_t*)&sAl[ab];
                al[1] = *(const uint32_t*)&sAl[ab + 8 * TSTR];
                al[2] = *(const uint32_t*)&sAl[ab + 8];
                al[3] = *(const uint32_t*)&sAl[ab + 8 * TSTR + 8];
#pragma unroll
                for (int nf = 0; nf < 4; nf++) {
                    mma_bf(acc[mf][nf], ah, bh[nf][0], bh[nf][1]);   // Ah*Bh
                    mma_bf(acc[mf][nf], ah, bl[nf][0], bl[nf][1]);   // Ah*Bl
                    mma_bf(acc[mf][nf], al, bh[nf][0], bh[nf][1]);   // Al*Bh
                }
            }
        }
    }

    // epilogue: frag (mf,nf): rows m0+wm*64+mf*16+{g, g+8}, cols +2*tig..+1
#pragma unroll
    for (int nf = 0; nf < 4; nf++) {
        int col = n0 + wn * 32 + nf * 8 + 2 * tig;
        float2 bb = *(const float2*)&bias[col];
#pragma unroll
        for (int mf = 0; mf < 4; mf++) {
            int row = m0 + wm * 64 + mf * 16 + g;
            float2 v0 = make_float2(acc[mf][nf][0] + bb.x, acc[mf][nf][1] + bb.y);
            float2 v1 = make_float2(acc[mf][nf][2] + bb.x, acc[mf][nf][3] + bb.y);
            *(float2*)&C[(size_t)row * ldc + col]       = v0;
            *(float2*)&C[(size_t)(row + 8) * ldc + col] = v1;
        }
    }
}

// ---------------- attention GEMM (FFMA2, 128x128x16 double-buffered) ---------
// out_w[i][u][:] = (sum_j w[u][i][j] * out[j][u][:]) / sumw[u][i]
__global__ __launch_bounds__(256, 2)
void attn_gemm()
{
    const int n0 = blockIdx.x * 128;
    const int m0 = blockIdx.y * 128;
    const int u  = blockIdx.z;
    const float* A = g_w    + (size_t)u * SS_ * SS_;
    const float* B = g_out  + (size_t)u * HH_;
    float*       C = g_outw + (size_t)u * HH_;
    const int lda = SS_, ldb = UU_ * HH_, ldc = UU_ * HH_;
    const int kmax = (SS_ < m0 + 128) ? SS_ : (m0 + 128);

    __shared__ float As[2][16][128];
    __shared__ float Bs[2][16][128];

    const int tid = threadIdx.x;
    const int tx4 = (tid & 15) * 4;
    const int ty4 = (tid >> 4) * 4;

    const int ar  = tid >> 1;
    const int akk = (tid & 1) * 8;
    const float* aRow = A + (size_t)(m0 + ar) * lda + akk;
    const int br  = tid >> 4;
    const int bcc = (tid & 15) * 8;
    const float* bPtr = B + (size_t)br * ldb + n0 + bcc;

    u64t acc[4][8];
#pragma unroll
    for (int i = 0; i < 4; i++)
#pragma unroll
        for (int j = 0; j < 8; j++) acc[i][j] = 0ULL;

    float4 pa0 = *(const float4*)(aRow);
    float4 pa1 = *(const float4*)(aRow + 4);
    float4 pb0 = *(const float4*)(bPtr);
    float4 pb1 = *(const float4*)(bPtr + 4);
    As[0][akk + 0][ar] = pa0.x; As[0][akk + 1][ar] = pa0.y;
    As[0][akk + 2][ar] = pa0.z; As[0][akk + 3][ar] = pa0.w;
    As[0][akk + 4][ar] = pa1.x; As[0][akk + 5][ar] = pa1.y;
    As[0][akk + 6][ar] = pa1.z; As[0][akk + 7][ar] = pa1.w;
    *(float4*)&Bs[0][br][bcc]     = pb0;
    *(float4*)&Bs[0][br][bcc + 4] = pb1;
    __syncthreads();

    const int nk = kmax >> 4;
    int buf = 0;
    for (int kt = 0; kt < nk; kt++) {
        if (kt + 1 < nk) {
            int kn = (kt + 1) << 4;
            pa0 = *(const float4*)(aRow + kn);
            pa1 = *(const float4*)(aRow + kn + 4);
            pb0 = *(const float4*)(bPtr + (size_t)kn * ldb);
            pb1 = *(const float4*)(bPtr + (size_t)kn * ldb + 4);
        }
#pragma unroll
        for (int k = 0; k < 16; k++) {
            float4 a0 = *(const float4*)&As[buf][k][ty4];
            float4 a1 = *(const float4*)&As[buf][k][64 + ty4];
            float4 b0 = *(const float4*)&Bs[buf][k][tx4];
            float4 b1 = *(const float4*)&Bs[buf][k][64 + tx4];
            u64t ap[4];
            ap[0] = pk2(a0.x, a0.y); ap[1] = pk2(a0.z, a0.w);
            ap[2] = pk2(a1.x, a1.y); ap[3] = pk2(a1.z, a1.w);
            u64t bd[8];
            bd[0] = pk2(b0.x, b0.x); bd[1] = pk2(b0.y, b0.y);
            bd[2] = pk2(b0.z, b0.z); bd[3] = pk2(b0.w, b0.w);
            bd[4] = pk2(b1.x, b1.x); bd[5] = pk2(b1.y, b1.y);
            bd[6] = pk2(b1.z, b1.z); bd[7] = pk2(b1.w, b1.w);
#pragma unroll
            for (int i = 0; i < 4; i++)
#pragma unroll
                for (int j = 0; j < 8; j++)
                    ffma2(acc[i][j], ap[i], bd[j]);
        }
        if (kt + 1 < nk) {
            int nb = buf ^ 1;
            As[nb][akk + 0][ar] = pa0.x; As[nb][akk + 1][ar] = pa0.y;
            As[nb][akk + 2][ar] = pa0.z; As[nb][akk + 3][ar] = pa0.w;
            As[nb][akk + 4][ar] = pa1.x; As[nb][akk + 5][ar] = pa1.y;
            As[nb][akk + 6][ar] = pa1.z; As[nb][akk + 7][ar] = pa1.w;
            *(float4*)&Bs[nb][br][bcc]     = pb0;
            *(float4*)&Bs[nb][br][bcc + 4] = pb1;
            __syncthreads();
            buf = nb;
        }
    }

#pragma unroll
    for (int mp = 0; mp < 4; mp++) {
        int r = m0 + ((mp >= 2) ? 64 : 0) + ty4 + (mp & 1) * 2;
        float2 v[8];
#pragma unroll
        for (int j = 0; j < 8; j++) v[j] = upk(acc[mp][j]);
        float s0 = 1.f / g_sumw[u * SS_ + r];
        float s1 = 1.f / g_sumw[u * SS_ + r + 1];
        float4 lo0 = make_float4(v[0].x * s0, v[1].x * s0, v[2].x * s0, v[3].x * s0);
        float4 lo1 = make_float4(v[4].x * s0, v[5].x * s0, v[6].x * s0, v[7].x * s0);
        float4 hi0 = make_float4(v[0].y * s1, v[1].y * s1, v[2].y * s1, v[3].y * s1);
        float4 hi1 = make_float4(v[4].y * s1, v[5].y * s1, v[6].y * s1, v[7].y * s1);
        float* c0 = C + (size_t)r * ldc + n0;
        float* c1 = C + (size_t)(r + 1) * ldc + n0;
        *(float4*)&c0[tx4]      = lo0;
        *(float4*)&c0[64 + tx4] = lo1;
        *(float4*)&c1[tx4]      = hi0;
        *(float4*)&c1[64 + tx4] = hi1;
    }
}

// ---------------- persistent GRU: all 512 steps in ONE kernel ----------------
__device__ __forceinline__ void grid_barrier(unsigned& target)
{
    __syncthreads();
    if (threadIdx.x == 0) {
        __threadfence();
        atomicAdd(&g_cnt, 1u);
        target += GRU_BLOCKS;
        while (*(volatile unsigned*)&g_cnt < target) { }
        __threadfence();
    }
    __syncthreads();
}

#define ASH_STRIDE 532

__global__ __launch_bounds__(GRU_THREADS)
void gru_persistent(const float* __restrict__ h0,
                    const float* __restrict__ bhh)
{
    extern __shared__ float dsm[];
    float* Wsh = dsm;                         // [256][96]
    float* Ash = dsm + 256 * 96;              // [32][ASH_STRIDE] dup pairs

    const int bz = blockIdx.x;
    const int kc = bz & 1;
    const int u0 = ((bz >> 1) & 3) * 32;
    const int n0 = (bz >> 3) * 96;
    const int kbase = kc * 256;

    const int tid = threadIdx.x;
    const int ty = tid >> 4;
    const int tx = tid & 15;

    for (int fi = tid; fi < 256 * 24; fi += GRU_THREADS) {
        int k = fi / 24, c = fi % 24;
        *(float4*)&Wsh[k * 96 + c * 4] =
            *(const float4*)&g_WhhT[(size_t)(kbase + k) * H3_ + n0 + c * 4];
    }

    const int fu = tid >> 3;
    const int fj = (tid & 7) * 4;

    unsigned target = 0;

    for (int st = 0; st < SS_; st++) {
        const float* hp = (st == 0) ? h0 : (g_out + (size_t)(st - 1) * UU_ * HH_);

        {
            const float* hrow = hp + (size_t)(u0 + fu) * HH_ + kbase;
            float* drow = &Ash[fu * ASH_STRIDE];
#pragma unroll
            for (int i = 0; i < 8; i++) {
                int kb = fj + 32 * i;
                float4 v = *(const float4*)&hrow[kb];
                float* d = &drow[2 * kb];
                *(float2*)&d[0] = make_float2(v.x, v.x);
                *(float2*)&d[2] = make_float2(v.y, v.y);
                *(float2*)&d[4] = make_float2(v.z, v.z);
                *(float2*)&d[6] = make_float2(v.w, v.w);
            }
        }
        __syncthreads();

        u64t acc[2][3];
        acc[0][0] = acc[0][1] = acc[0][2] = 0ULL;
        acc[1][0] = acc[1][1] = acc[1][2] = 0ULL;
        const float* arow0 = &Ash[(ty * 2 + 0) * ASH_STRIDE];
        const float* arow1 = &Ash[(ty * 2 + 1) * ASH_STRIDE];
        const float* bcol  = &Wsh[tx * 6];
#pragma unroll 8
        for (int k = 0; k < 256; k++) {
            u64t a0 = *(const u64t*)&arow0[2 * k];
            u64t a1 = *(const u64t*)&arow1[2 * k];
            const float* bk = bcol + k * 96;
            u64t b0 = *(const u64t*)&bk[0];
            u64t b1 = *(const u64t*)&bk[2];
            u64t b2 = *(const u64t*)&bk[4];
            ffma2(acc[0][0], a0, b0); ffma2(acc[0][1], a0, b1); ffma2(acc[0][2], a0, b2);
            ffma2(acc[1][0], a1, b0); ffma2(acc[1][1], a1, b1); ffma2(acc[1][2], a1, b2);
        }
#pragma unroll
        for (int uu = 0; uu < 2; uu++) {
            float* dst = g_ghp + (size_t)(kc * UU_ + u0 + ty * 2 + uu) * H3_ + n0 + tx * 6;
            float2 w0 = upk(acc[uu][0]);
            float2 w1 = upk(acc[uu][1]);
            float2 w2 = upk(acc[uu][2]);
            *(float2*)&dst[0] = w0;
            *(float2*)&dst[2] = w1;
            *(float2*)&dst[4] = w2;
        }

        grid_barrier(target);

#pragma unroll
        for (int e = 0; e < 2; e++) {
            int idx = e * (GRU_BLOCKS * GRU_THREADS) + bz * GRU_THREADS + tid;
            int u = idx >> 9;
            int j = idx & 511;
            const float* p0 = g_ghp + (size_t)u * H3_;
            const float* p1 = g_ghp + (size_t)(UU_ + u) * H3_;
            float hr = p0[j]        + p1[j]        + bhh[j];
            float hz = p0[512 + j]  + p1[512 + j]  + bhh[512 + j];
            float hn = p0[1024 + j] + p1[1024 + j] + bhh[1024 + j];
            const float* gi = g_gi + ((size_t)st * UU_ + u) * H3_;
            float r = 1.f / (1.f + __expf(-(gi[j] + hr)));
            float z = 1.f / (1.f + __expf(-(gi[512 + j] + hz)));
            float a = gi[1024 + j] + r * hn;
            float e2 = __expf(2.f * a);
            float n = 1.f - 2.f / (e2 + 1.f);
            float hprev = hp[(size_t)u * HH_ + j];
            g_out[(size_t)st * UU_ * HH_ + idx] = (1.f - z) * n + z * hprev;
        }

        grid_barrier(target);
    }
}

// ---------------- causal spatiotemporal weight matrix ------------------------
__global__ void wmat_kernel()
{
    const int i = blockIdx.x;
    const int u = blockIdx.y;
    const float ti  = g_tT[u * SS_ + i];
    const float sxi = g_sx[u * SS_ + i];
    const float syi = g_sy[u * SS_ + i];

    float lsum = 0.f;
    for (int j = threadIdx.x; j < SS_; j += 256) {
        float wv = 0.f;
        if (j <= i) {
            float dt = ti - g_tT[u * SS_ + j];
            float dx = sxi - g_sx[u * SS_ + j];
            float dy = syi - g_sy[u * SS_ + j];
            float ds = sqrtf(dx * dx + dy * dy);
            wv = __expf(-dt * (F_LT / F_DAY) - F_LS * ds) + 1e-10f;
        }
        g_w[((size_t)u * SS_ + i) * SS_ + j] = wv;
        lsum += wv;
    }
    __shared__ float red[256];
    red[threadIdx.x] = lsum;
    __syncthreads();
    for (int o = 128; o > 0; o >>= 1) {
        if (threadIdx.x < o) red[threadIdx.x] += red[threadIdx.x + o];
        __syncthreads();
    }
    if (threadIdx.x == 0) g_sumw[u * SS_ + i] = red[0];
}

// copy h_last = out[S-1] to tail of d_out
__global__ void hlast_kernel(float* __restrict__ out)
{
    int i = blockIdx.x * blockDim.x + threadIdx.x;
    if (i < UU_ * HH_)
        out[(size_t)SS_ * UU_ * VV_ + i] = g_out[(size_t)(SS_ - 1) * UU_ * HH_ + i];
}

// ---------------- launcher ---------------------------------------------------
extern "C" void kernel_launch(void* const* d_in, const int* in_sizes, int n_in,
                              void* d_out, int out_size)
{
    const int*   x   = (const int*)d_in[0];
    const float* t   = (const float*)d_in[1];
    const float* s   = (const float*)d_in[2];
    // d_in[3] y_t, d_in[4] y_s, d_in[6] active_user: unused by reference
    const float* h0  = (const float*)d_in[5];
    const float* emb = (const float*)d_in[7];
    const float* Wih = (const float*)d_in[8];
    const float* Whh = (const float*)d_in[9];
    const float* bih = (const float*)d_in[10];
    const float* bhh = (const float*)d_in[11];
    const float* fcw = (const float*)d_in[12];
    const float* fcb = (const float*)d_in[13];
    float* out = (float*)d_out;

    static const int GRU_SMEM = (256 * 96 + 32 * ASH_STRIDE) * 4;
    cudaFuncSetAttribute(gru_persistent,
                         cudaFuncAttributeMaxDynamicSharedMemorySize, GRU_SMEM);

    // 1. W_hh transpose + t/s relayout + barrier reset
    prep_kernel<<<(HH_ * H3_ + 255) / 256, 256>>>(Whh, t, s);

    // 2. gi = emb[x] @ W_ih^T + b_ih   (mma.sync split-bf16; B = original W_ih)
    tgemm<0><<<dim3(H3_ / 128, (SS_ * UU_) / 128), 256>>>(x, emb, Wih, bih, nullptr);

    // 3. GRU recurrence: 512 steps inside ONE persistent kernel
    gru_persistent<<<GRU_BLOCKS, GRU_THREADS, GRU_SMEM>>>(h0, bhh);

    // 4. causal spatiotemporal weights + row sums
    wmat_kernel<<<dim3(SS_, UU_), 256>>>();

    // 5. out_w = (w @ out) / sum_w   (FFMA2, triangular K-limit)
    attn_gemm<<<dim3(HH_ / 128, SS_ / 128, UU_), 256>>>();

    // 6. y = out_w @ fc_w^T + fc_b   (mma.sync split-bf16; B = original fc_w)
    tgemm<1><<<dim3(VV_ / 128, (SS_ * UU_) / 128), 256>>>(nullptr, nullptr, fcw, fcb, out);

    // 7. h_last
    hlast_kernel<<<(UU_ * HH_ + 255) / 256, 256>>>(out);
}

// round 10
// speedup vs baseline: 1.6862x; 1.2172x over previous
#include <cuda_runtime.h>
#include <cuda_bf16.h>
#include <math.h>
#include <stdint.h>

// Problem constants
#define SS_ 512   // sequence
#define UU_ 128   // users (batch)
#define HH_ 512   // hidden
#define H3_ 1536  // 3*H
#define VV_ 2048  // vocab
#define F_DAY 86400.0f
#define F_LT  0.1f
#define F_LS  1.0f

#define GRU_BLOCKS 128
#define GRU_THREADS 256

typedef unsigned long long u64t;

// ---------------- packed fp32x2 helpers (Blackwell FFMA2) --------------------
__device__ __forceinline__ u64t pk2(float lo, float hi) {
    u64t r; asm("mov.b64 %0, {%1, %2};" : "=l"(r) : "f"(lo), "f"(hi)); return r;
}
__device__ __forceinline__ void ffma2(u64t& d, u64t a, u64t b) {
    asm("fma.rn.f32x2 %0, %1, %2, %0;" : "+l"(d) : "l"(a), "l"(b));
}
__device__ __forceinline__ float2 upk(u64t v) {
    float2 r; asm("mov.b64 {%0, %1}, %2;" : "=f"(r.x), "=f"(r.y) : "l"(v)); return r;
}

// ---------------- bf16 helpers ----------------------------------------------
__device__ __forceinline__ uint32_t pack_bf2(float a, float b) {
    __nv_bfloat162 t = __floats2bfloat162_rn(a, b);
    return *reinterpret_cast<uint32_t*>(&t);
}
__device__ __forceinline__ void mma_bf(float* d, const uint32_t* a, uint32_t b0, uint32_t b1) {
    asm volatile(
        "mma.sync.aligned.m16n8k16.row.col.f32.bf16.bf16.f32 "
        "{%0,%1,%2,%3}, {%4,%5,%6,%7}, {%8,%9}, {%0,%1,%2,%3};"
        : "+f"(d[0]), "+f"(d[1]), "+f"(d[2]), "+f"(d[3])
        : "r"(a[0]), "r"(a[1]), "r"(a[2]), "r"(a[3]), "r"(b0), "r"(b1));
}
// split float4 into bf16-hi and bf16-lo packed pairs
__device__ __forceinline__ void cvt4(float4 v, uint2& h, uint2& l) {
    float hx = __bfloat162float(__float2bfloat16_rn(v.x));
    float hy = __bfloat162float(__float2bfloat16_rn(v.y));
    float hz = __bfloat162float(__float2bfloat16_rn(v.z));
    float hw = __bfloat162float(__float2bfloat16_rn(v.w));
    h = make_uint2(pack_bf2(hx, hy), pack_bf2(hz, hw));
    l = make_uint2(pack_bf2(v.x - hx, v.y - hy), pack_bf2(v.z - hz, v.w - hw));
}

// ---------------- scratch (device globals; allocation is banned) -------------
__device__ float g_P[(size_t)VV_ * H3_];          // P = emb @ Wih^T + bih  (12.6MB, L2)
__device__ float g_out[(size_t)SS_ * UU_ * HH_];  // [S][U][H]  GRU outputs
__device__ __nv_bfloat16 g_outw_h[(size_t)SS_ * UU_ * HH_];  // outw split hi
__device__ __nv_bfloat16 g_outw_l[(size_t)SS_ * UU_ * HH_];  // outw split lo
__device__ float g_w[(size_t)UU_ * SS_ * SS_];    // [U][S][S]  causal weights
__device__ float g_sumw[UU_ * SS_];               // [U][S]
__device__ float g_WihT[HH_ * H3_];               // [K=H][N=3H] for P gemm
__device__ float g_WhhT[HH_ * H3_];               // [K=H][N=3H] for GRU
__device__ __nv_bfloat16 g_fcw_h[(size_t)VV_ * HH_];  // fc_w split hi
__device__ __nv_bfloat16 g_fcw_l[(size_t)VV_ * HH_];  // fc_w split lo
__device__ float g_tT[UU_ * SS_];                 // t transposed [U][S]
__device__ float g_sx[UU_ * SS_];
__device__ float g_sy[UU_ * SS_];
__device__ float g_ghp[2 * UU_ * H3_];            // split-K partials of gh
__device__ unsigned g_cnt;                        // global barrier counter

// ---------------- prep: transposes + fcw split + t/s + barrier reset ---------
__global__ void prep_kernel(const float* __restrict__ Wih,
                            const float* __restrict__ Whh,
                            const float* __restrict__ fcw,
                            const float* __restrict__ t,
                            const float* __restrict__ s)
{
    int idx = blockIdx.x * blockDim.x + threadIdx.x;
    if (idx == 0) g_cnt = 0;                      // reset software barrier each replay
    if (idx < HH_ * H3_) {
        int k = idx / H3_, n = idx % H3_;
        g_WihT[idx] = Wih[(size_t)n * HH_ + k];
        g_WhhT[idx] = Whh[(size_t)n * HH_ + k];
    }
    if (idx < VV_ * HH_) {
        float f = fcw[idx];
        __nv_bfloat16 h = __float2bfloat16_rn(f);
        g_fcw_h[idx] = h;
        g_fcw_l[idx] = __float2bfloat16_rn(f - __bfloat162float(h));
    }
    if (idx < UU_ * SS_) {
        int u = idx / SS_, i = idx % SS_;
        g_tT[idx] = t[(size_t)i * UU_ + u];
        g_sx[idx] = s[((size_t)i * UU_ + u) * 2 + 0];
        g_sy[idx] = s[((size_t)i * UU_ + u) * 2 + 1];
    }
}

// ---------------- P GEMM: P = emb @ Wih^T + bih (FFMA2 128x128x16) -----------
// M=2048 (vocab), N=1536, K=512 — only 3.2 GFLOP, runs once.
__global__ __launch_bounds__(256, 2)
void pgemm(const float* __restrict__ emb, const float* __restrict__ bih)
{
    const int n0 = blockIdx.x * 128;
    const int m0 = blockIdx.y * 128;
    const float* A = emb;     const int lda = HH_;
    const float* B = g_WihT;  const int ldb = H3_;
    float*       C = g_P;     const int ldc = H3_;

    __shared__ float As[2][16][128];
    __shared__ float Bs[2][16][128];

    const int tid = threadIdx.x;
    const int tx4 = (tid & 15) * 4;
    const int ty4 = (tid >> 4) * 4;

    const int ar  = tid >> 1;
    const int akk = (tid & 1) * 8;
    const float* aRow = A + (size_t)(m0 + ar) * lda + akk;
    const int br  = tid >> 4;
    const int bcc = (tid & 15) * 8;
    const float* bPtr = B + (size_t)br * ldb + n0 + bcc;

    u64t acc[4][8];
#pragma unroll
    for (int i = 0; i < 4; i++)
#pragma unroll
        for (int j = 0; j < 8; j++) acc[i][j] = 0ULL;

    float4 pa0 = *(const float4*)(aRow);
    float4 pa1 = *(const float4*)(aRow + 4);
    float4 pb0 = *(const float4*)(bPtr);
    float4 pb1 = *(const float4*)(bPtr + 4);
    As[0][akk + 0][ar] = pa0.x; As[0][akk + 1][ar] = pa0.y;
    As[0][akk + 2][ar] = pa0.z; As[0][akk + 3][ar] = pa0.w;
    As[0][akk + 4][ar] = pa1.x; As[0][akk + 5][ar] = pa1.y;
    As[0][akk + 6][ar] = pa1.z; As[0][akk + 7][ar] = pa1.w;
    *(float4*)&Bs[0][br][bcc]     = pb0;
    *(float4*)&Bs[0][br][bcc + 4] = pb1;
    __syncthreads();

    const int nk = HH_ >> 4;
    int buf = 0;
    for (int kt = 0; kt < nk; kt++) {
        if (kt + 1 < nk) {
            int kn = (kt + 1) << 4;
            pa0 = *(const float4*)(aRow + kn);
            pa1 = *(const float4*)(aRow + kn + 4);
            pb0 = *(const float4*)(bPtr + (size_t)kn * ldb);
            pb1 = *(const float4*)(bPtr + (size_t)kn * ldb + 4);
        }
#pragma unroll
        for (int k = 0; k < 16; k++) {
            float4 a0 = *(const float4*)&As[buf][k][ty4];
            float4 a1 = *(const float4*)&As[buf][k][64 + ty4];
            float4 b0 = *(const float4*)&Bs[buf][k][tx4];
            float4 b1 = *(const float4*)&Bs[buf][k][64 + tx4];
            u64t ap[4];
            ap[0] = pk2(a0.x, a0.y); ap[1] = pk2(a0.z, a0.w);
            ap[2] = pk2(a1.x, a1.y); ap[3] = pk2(a1.z, a1.w);
            u64t bd[8];
            bd[0] = pk2(b0.x, b0.x); bd[1] = pk2(b0.y, b0.y);
            bd[2] = pk2(b0.z, b0.z); bd[3] = pk2(b0.w, b0.w);
            bd[4] = pk2(b1.x, b1.x); bd[5] = pk2(b1.y, b1.y);
            bd[6] = pk2(b1.z, b1.z); bd[7] = pk2(b1.w, b1.w);
#pragma unroll
            for (int i = 0; i < 4; i++)
#pragma unroll
                for (int j = 0; j < 8; j++)
                    ffma2(acc[i][j], ap[i], bd[j]);
        }
        if (kt + 1 < nk) {
            int nb = buf ^ 1;
            As[nb][akk + 0][ar] = pa0.x; As[nb][akk + 1][ar] = pa0.y;
            As[nb][akk + 2][ar] = pa0.z; As[nb][akk + 3][ar] = pa0.w;
            As[nb][akk + 4][ar] = pa1.x; As[nb][akk + 5][ar] = pa1.y;
            As[nb][akk + 6][ar] = pa1.z; As[nb][akk + 7][ar] = pa1.w;
            *(float4*)&Bs[nb][br][bcc]     = pb0;
            *(float4*)&Bs[nb][br][bcc + 4] = pb1;
            __syncthreads();
            buf = nb;
        }
    }

    float bv[8];
#pragma unroll
    for (int j = 0; j < 8; j++)
        bv[j] = bih[n0 + ((j < 4) ? (tx4 + j) : (64 + tx4 + j - 4))];
#pragma unroll
    for (int mp = 0; mp < 4; mp++) {
        int r = m0 + ((mp >= 2) ? 64 : 0) + ty4 + (mp & 1) * 2;
        float2 v[8];
#pragma unroll
        for (int j = 0; j < 8; j++) v[j] = upk(acc[mp][j]);
        float4 lo0 = make_float4(v[0].x + bv[0], v[1].x + bv[1], v[2].x + bv[2], v[3].x + bv[3]);
        float4 lo1 = make_float4(v[4].x + bv[4], v[5].x + bv[5], v[6].x + bv[6], v[7].x + bv[7]);
        float4 hi0 = make_float4(v[0].y + bv[0], v[1].y + bv[1], v[2].y + bv[2], v[3].y + bv[3]);
        float4 hi1 = make_float4(v[4].y + bv[4], v[5].y + bv[5], v[6].y + bv[6], v[7].y + bv[7]);
        float* c0 = C + (size_t)r * ldc + n0;
        float* c1 = C + (size_t)(r + 1) * ldc + n0;
        *(float4*)&c0[tx4]      = lo0;
        *(float4*)&c0[64 + tx4] = lo1;
        *(float4*)&c1[tx4]      = hi0;
        *(float4*)&c1[64 + tx4] = hi1;
    }
}

// ---------------- fc GEMM: split-bf16 mma.sync, preconverted operands --------
// y[m][n] = sum_k outw[m][k]*fcw[n][k] + fcb[n];  Ah*Bh + Ah*Bl + Al*Bh
#define TSTR 40   // smem row stride in bf16 (conflict-free frag loads)

__global__ __launch_bounds__(256, 2)
void tgemm_fc(const float* __restrict__ bias, float* __restrict__ Cout)
{
    __shared__ uint16_t sAh[128 * TSTR];
    __shared__ uint16_t sAl[128 * TSTR];
    __shared__ uint16_t sBh[128 * TSTR];
    __shared__ uint16_t sBl[128 * TSTR];

    const int tid = threadIdx.x;
    const int wid = tid >> 5, lid = tid & 31;
    const int g   = lid >> 2, tig = lid & 3;
    const int wm  = wid & 1;
    const int wn  = wid >> 1;
    const int n0  = blockIdx.x * 128;
    const int m0  = blockIdx.y * 128;

    // fill mapping: thread covers row fr, k-half kh (16 bf16 = 2x uint4)
    const int fr = tid >> 1;
    const int kh = (tid & 1) * 16;
    const uint16_t* ahS = (const uint16_t*)g_outw_h + (size_t)(m0 + fr) * HH_ + kh;
    const uint16_t* alS = (const uint16_t*)g_outw_l + (size_t)(m0 + fr) * HH_ + kh;
    const uint16_t* bhS = (const uint16_t*)g_fcw_h  + (size_t)(n0 + fr) * HH_ + kh;
    const uint16_t* blS = (const uint16_t*)g_fcw_l  + (size_t)(n0 + fr) * HH_ + kh;
    uint4* ahD = (uint4*)&sAh[fr * TSTR + kh];
    uint4* alD = (uint4*)&sAl[fr * TSTR + kh];
    uint4* bhD = (uint4*)&sBh[fr * TSTR + kh];
    uint4* blD = (uint4*)&sBl[fr * TSTR + kh];

    float acc[4][4][4];
#pragma unroll
    for (int i = 0; i < 4; i++)
#pragma unroll
        for (int j = 0; j < 4; j++)
#pragma unroll
            for (int q = 0; q < 4; q++) acc[i][j][q] = 0.f;

    for (int kb = 0; kb < HH_; kb += 32) {
        __syncthreads();
        {
            const uint4* p;
            p = (const uint4*)(ahS + kb); ahD[0] = p[0]; ahD[1] = p[1];
            p = (const uint4*)(alS + kb); alD[0] = p[0]; alD[1] = p[1];
            p = (const uint4*)(bhS + kb); bhD[0] = p[0]; bhD[1] = p[1];
            p = (const uint4*)(blS + kb); blD[0] = p[0]; blD[1] = p[1];
        }
        __syncthreads();
#pragma unroll
        for (int k16 = 0; k16 < 32; k16 += 16) {
            uint32_t bh[4][2], bl[4][2];
#pragma unroll
            for (int nf = 0; nf < 4; nf++) {
                int nb = (wn * 32 + nf * 8 + g) * TSTR + k16 + 2 * tig;
                bh[nf][0] = *(const uint32_t*)&sBh[nb];
                bh[nf][1] = *(const uint32_t*)&sBh[nb + 8];
                bl[nf][0] = *(const uint32_t*)&sBl[nb];
                bl[nf][1] = *(const uint32_t*)&sBl[nb + 8];
            }
#pragma unroll
            for (int mf = 0; mf < 4; mf++) {
                int ab = (wm * 64 + mf * 16 + g) * TSTR + k16 + 2 * tig;
                uint32_t ah[4], al[4];
                ah[0] = *(const uint32_t*)&sAh[ab];
                ah[1] = *(const uint32_t*)&sAh[ab + 8 * TSTR];
                ah[2] = *(const uint32_t*)&sAh[ab + 8];
                ah[3] = *(const uint32_t*)&sAh[ab + 8 * TSTR + 8];
                al[0] = *(const uint32_t*)&sAl[ab];
                al[1] = *(const uint32_t*)&sAl[ab + 8 * TSTR];
                al[2] = *(const uint32_t*)&sAl[ab + 8];
                al[3] = *(const uint32_t*)&sAl[ab + 8 * TSTR + 8];
#pragma unroll
                for (int nf = 0; nf < 4; nf++) {
                    mma_bf(acc[mf][nf], ah, bh[nf][0], bh[nf][1]);   // Ah*Bh
                    mma_bf(acc[mf][nf], ah, bl[nf][0], bl[nf][1]);   // Ah*Bl
                    mma_bf(acc[mf][nf], al, bh[nf][0], bh[nf][1]);   // Al*Bh
                }
            }
        }
    }

#pragma unroll
    for (int nf = 0; nf < 4; nf++) {
        int col = n0 + wn * 32 + nf * 8 + 2 * tig;
        float2 bb = *(const float2*)&bias[col];
#pragma unroll
        for (int mf = 0; mf < 4; mf++) {
            int row = m0 + wm * 64 + mf * 16 + g;
            float2 v0 = make_float2(acc[mf][nf][0] + bb.x, acc[mf][nf][1] + bb.y);
            float2 v1 = make_float2(acc[mf][nf][2] + bb.x, acc[mf][nf][3] + bb.y);
            *(float2*)&Cout[(size_t)row * VV_ + col]       = v0;
            *(float2*)&Cout[(size_t)(row + 8) * VV_ + col] = v1;
        }
    }
}

// ---------------- attention GEMM (FFMA2) -> bf16 hi/lo outw ------------------
__global__ __launch_bounds__(256, 2)
void attn_gemm()
{
    const int n0 = blockIdx.x * 128;
    const int m0 = blockIdx.y * 128;
    const int u  = blockIdx.z;
    const float* A = g_w   + (size_t)u * SS_ * SS_;
    const float* B = g_out + (size_t)u * HH_;
    __nv_bfloat16* Ch = g_outw_h + (size_t)u * HH_;
    __nv_bfloat16* Cl = g_outw_l + (size_t)u * HH_;
    const int lda = SS_, ldb = UU_ * HH_, ldc = UU_ * HH_;
    const int kmax = (SS_ < m0 + 128) ? SS_ : (m0 + 128);

    __shared__ float As[2][16][128];
    __shared__ float Bs[2][16][128];

    const int tid = threadIdx.x;
    const int tx4 = (tid & 15) * 4;
    const int ty4 = (tid >> 4) * 4;

    const int ar  = tid >> 1;
    const int akk = (tid & 1) * 8;
    const float* aRow = A + (size_t)(m0 + ar) * lda + akk;
    const int br  = tid >> 4;
    const int bcc = (tid & 15) * 8;
    const float* bPtr = B + (size_t)br * ldb + n0 + bcc;

    u64t acc[4][8];
#pragma unroll
    for (int i = 0; i < 4; i++)
#pragma unroll
        for (int j = 0; j < 8; j++) acc[i][j] = 0ULL;

    float4 pa0 = *(const float4*)(aRow);
    float4 pa1 = *(const float4*)(aRow + 4);
    float4 pb0 = *(const float4*)(bPtr);
    float4 pb1 = *(const float4*)(bPtr + 4);
    As[0][akk + 0][ar] = pa0.x; As[0][akk + 1][ar] = pa0.y;
    As[0][akk + 2][ar] = pa0.z; As[0][akk + 3][ar] = pa0.w;
    As[0][akk + 4][ar] = pa1.x; As[0][akk + 5][ar] = pa1.y;
    As[0][akk + 6][ar] = pa1.z; As[0][akk + 7][ar] = pa1.w;
    *(float4*)&Bs[0][br][bcc]     = pb0;
    *(float4*)&Bs[0][br][bcc + 4] = pb1;
    __syncthreads();

    const int nk = kmax >> 4;
    int buf = 0;
    for (int kt = 0; kt < nk; kt++) {
        if (kt + 1 < nk) {
            int kn = (kt + 1) << 4;
            pa0 = *(const float4*)(aRow + kn);
            pa1 = *(const float4*)(aRow + kn + 4);
            pb0 = *(const float4*)(bPtr + (size_t)kn * ldb);
            pb1 = *(const float4*)(bPtr + (size_t)kn * ldb + 4);
        }
#pragma unroll
        for (int k = 0; k < 16; k++) {
            float4 a0 = *(const float4*)&As[buf][k][ty4];
            float4 a1 = *(const float4*)&As[buf][k][64 + ty4];
            float4 b0 = *(const float4*)&Bs[buf][k][tx4];
            float4 b1 = *(const float4*)&Bs[buf][k][64 + tx4];
            u64t ap[4];
            ap[0] = pk2(a0.x, a0.y); ap[1] = pk2(a0.z, a0.w);
            ap[2] = pk2(a1.x, a1.y); ap[3] = pk2(a1.z, a1.w);
            u64t bd[8];
            bd[0] = pk2(b0.x, b0.x); bd[1] = pk2(b0.y, b0.y);
            bd[2] = pk2(b0.z, b0.z); bd[3] = pk2(b0.w, b0.w);
            bd[4] = pk2(b1.x, b1.x); bd[5] = pk2(b1.y, b1.y);
            bd[6] = pk2(b1.z, b1.z); bd[7] = pk2(b1.w, b1.w);
#pragma unroll
            for (int i = 0; i < 4; i++)
#pragma unroll
                for (int j = 0; j < 8; j++)
                    ffma2(acc[i][j], ap[i], bd[j]);
        }
        if (kt + 1 < nk) {
            int nb = buf ^ 1;
            As[nb][akk + 0][ar] = pa0.x; As[nb][akk + 1][ar] = pa0.y;
            As[nb][akk + 2][ar] = pa0.z; As[nb][akk + 3][ar] = pa0.w;
            As[nb][akk + 4][ar] = pa1.x; As[nb][akk + 5][ar] = pa1.y;
            As[nb][akk + 6][ar] = pa1.z; As[nb][akk + 7][ar] = pa1.w;
            *(float4*)&Bs[nb][br][bcc]     = pb0;
            *(float4*)&Bs[nb][br][bcc + 4] = pb1;
            __syncthreads();
            buf = nb;
        }
    }

#pragma unroll
    for (int mp = 0; mp < 4; mp++) {
        int r = m0 + ((mp >= 2) ? 64 : 0) + ty4 + (mp & 1) * 2;
        float2 v[8];
#pragma unroll
        for (int j = 0; j < 8; j++) v[j] = upk(acc[mp][j]);
        float s0 = 1.f / g_sumw[u * SS_ + r];
        float s1 = 1.f / g_sumw[u * SS_ + r + 1];
        float4 lo0 = make_float4(v[0].x * s0, v[1].x * s0, v[2].x * s0, v[3].x * s0);
        float4 lo1 = make_float4(v[4].x * s0, v[5].x * s0, v[6].x * s0, v[7].x * s0);
        float4 hi0 = make_float4(v[0].y * s1, v[1].y * s1, v[2].y * s1, v[3].y * s1);
        float4 hi1 = make_float4(v[4].y * s1, v[5].y * s1, v[6].y * s1, v[7].y * s1);
        uint2 h, l;
        size_t b0 = (size_t)r * ldc, b1 = (size_t)(r + 1) * ldc;
        cvt4(lo0, h, l); *(uint2*)&Ch[b0 + n0 + tx4] = h;      *(uint2*)&Cl[b0 + n0 + tx4] = l;
        cvt4(lo1, h, l); *(uint2*)&Ch[b0 + n0 + 64 + tx4] = h; *(uint2*)&Cl[b0 + n0 + 64 + tx4] = l;
        cvt4(hi0, h, l); *(uint2*)&Ch[b1 + n0 + tx4] = h;      *(uint2*)&Cl[b1 + n0 + tx4] = l;
        cvt4(hi1, h, l); *(uint2*)&Ch[b1 + n0 + 64 + tx4] = h; *(uint2*)&Cl[b1 + n0 + 64 + tx4] = l;
    }
}

// ---------------- persistent GRU: all 512 steps in ONE kernel ----------------
__device__ __forceinline__ void grid_barrier(unsigned& target)
{
    __syncthreads();
    if (threadIdx.x == 0) {
        __threadfence();
        atomicAdd(&g_cnt, 1u);
        target += GRU_BLOCKS;
        while (*(volatile unsigned*)&g_cnt < target) { }
        __threadfence();
    }
    __syncthreads();
}

#define ASH_STRIDE 532

__global__ __launch_bounds__(GRU_THREADS)
void gru_persistent(const float* __restrict__ h0,
                    const float* __restrict__ bhh,
                    const int* __restrict__ x)
{
    extern __shared__ float dsm[];
    float* Wsh = dsm;                         // [256][96]
    float* Ash = dsm + 256 * 96;              // [32][ASH_STRIDE] dup pairs

    const int bz = blockIdx.x;
    const int kc = bz & 1;
    const int u0 = ((bz >> 1) & 3) * 32;
    const int n0 = (bz >> 3) * 96;
    const int kbase = kc * 256;

    const int tid = threadIdx.x;
    const int ty = tid >> 4;
    const int tx = tid & 15;

    for (int fi = tid; fi < 256 * 24; fi += GRU_THREADS) {
        int k = fi / 24, c = fi % 24;
        *(float4*)&Wsh[k * 96 + c * 4] =
            *(const float4*)&g_WhhT[(size_t)(kbase + k) * H3_ + n0 + c * 4];
    }

    const int fu = tid >> 3;
    const int fj = (tid & 7) * 4;

    unsigned target = 0;

    for (int st = 0; st < SS_; st++) {
        const float* hp = (st == 0) ? h0 : (g_out + (size_t)(st - 1) * UU_ * HH_);

        {
            const float* hrow = hp + (size_t)(u0 + fu) * HH_ + kbase;
            float* drow = &Ash[fu * ASH_STRIDE];
#pragma unroll
            for (int i = 0; i < 8; i++) {
                int kb = fj + 32 * i;
                float4 v = *(const float4*)&hrow[kb];
                float* d = &drow[2 * kb];
                *(float2*)&d[0] = make_float2(v.x, v.x);
                *(float2*)&d[2] = make_float2(v.y, v.y);
                *(float2*)&d[4] = make_float2(v.z, v.z);
                *(float2*)&d[6] = make_float2(v.w, v.w);
            }
        }
        __syncthreads();

        u64t acc[2][3];
        acc[0][0] = acc[0][1] = acc[0][2] = 0ULL;
        acc[1][0] = acc[1][1] = acc[1][2] = 0ULL;
        const float* arow0 = &Ash[(ty * 2 + 0) * ASH_STRIDE];
        const float* arow1 = &Ash[(ty * 2 + 1) * ASH_STRIDE];
        const float* bcol  = &Wsh[tx * 6];
#pragma unroll 8
        for (int k = 0; k < 256; k++) {
            u64t a0 = *(const u64t*)&arow0[2 * k];
            u64t a1 = *(const u64t*)&arow1[2 * k];
            const float* bk = bcol + k * 96;
            u64t b0 = *(const u64t*)&bk[0];
            u64t b1 = *(const u64t*)&bk[2];
            u64t b2 = *(const u64t*)&bk[4];
            ffma2(acc[0][0], a0, b0); ffma2(acc[0][1], a0, b1); ffma2(acc[0][2], a0, b2);
            ffma2(acc[1][0], a1, b0); ffma2(acc[1][1], a1, b1); ffma2(acc[1][2], a1, b2);
        }
#pragma unroll
        for (int uu = 0; uu < 2; uu++) {
            float* dst = g_ghp + (size_t)(kc * UU_ + u0 + ty * 2 + uu) * H3_ + n0 + tx * 6;
            float2 w0 = upk(acc[uu][0]);
            float2 w1 = upk(acc[uu][1]);
            float2 w2 = upk(acc[uu][2]);
            *(float2*)&dst[0] = w0;
            *(float2*)&dst[2] = w1;
            *(float2*)&dst[4] = w2;
        }

        grid_barrier(target);

#pragma unroll
        for (int e = 0; e < 2; e++) {
            int idx = e * (GRU_BLOCKS * GRU_THREADS) + bz * GRU_THREADS + tid;
            int u = idx >> 9;
            int j = idx & 511;
            const float* p0 = g_ghp + (size_t)u * H3_;
            const float* p1 = g_ghp + (size_t)(UU_ + u) * H3_;
            float hr = p0[j]        + p1[j]        + bhh[j];
            float hz = p0[512 + j]  + p1[512 + j]  + bhh[512 + j];
            float hn = p0[1024 + j] + p1[1024 + j] + bhh[1024 + j];
            // gi gathered from L2-resident P table (replaces materialized g_gi)
            const float* gi = g_P + (size_t)__ldg(&x[st * UU_ + u]) * H3_;
            float r = 1.f / (1.f + __expf(-(gi[j] + hr)));
            float z = 1.f / (1.f + __expf(-(gi[512 + j] + hz)));
            float a = gi[1024 + j] + r * hn;
            float e2 = __expf(2.f * a);
            float n = 1.f - 2.f / (e2 + 1.f);
            float hprev = hp[(size_t)u * HH_ + j];
            g_out[(size_t)st * UU_ * HH_ + idx] = (1.f - z) * n + z * hprev;
        }

        grid_barrier(target);
    }
}

// ---------------- causal spatiotemporal weight matrix ------------------------
__global__ void wmat_kernel()
{
    const int i = blockIdx.x;
    const int u = blockIdx.y;
    const float ti  = g_tT[u * SS_ + i];
    const float sxi = g_sx[u * SS_ + i];
    const float syi = g_sy[u * SS_ + i];

    float lsum = 0.f;
    for (int j = threadIdx.x; j < SS_; j += 256) {
        float wv = 0.f;
        if (j <= i) {
            float dt = ti - g_tT[u * SS_ + j];
            float dx = sxi - g_sx[u * SS_ + j];
            float dy = syi - g_sy[u * SS_ + j];
            float ds = sqrtf(dx * dx + dy * dy);
            wv = __expf(-dt * (F_LT / F_DAY) - F_LS * ds) + 1e-10f;
        }
        g_w[((size_t)u * SS_ + i) * SS_ + j] = wv;
        lsum += wv;
    }
    __shared__ float red[256];
    red[threadIdx.x] = lsum;
    __syncthreads();
    for (int o = 128; o > 0; o >>= 1) {
        if (threadIdx.x < o) red[threadIdx.x] += red[threadIdx.x + o];
        __syncthreads();
    }
    if (threadIdx.x == 0) g_sumw[u * SS_ + i] = red[0];
}

// copy h_last = out[S-1] to tail of d_out
__global__ void hlast_kernel(float* __restrict__ out)
{
    int i = blockIdx.x * blockDim.x + threadIdx.x;
    if (i < UU_ * HH_)
        out[(size_t)SS_ * UU_ * VV_ + i] = g_out[(size_t)(SS_ - 1) * UU_ * HH_ + i];
}

// ---------------- launcher ---------------------------------------------------
extern "C" void kernel_launch(void* const* d_in, const int* in_sizes, int n_in,
                              void* d_out, int out_size)
{
    const int*   x   = (const int*)d_in[0];
    const float* t   = (const float*)d_in[1];
    const float* s   = (const float*)d_in[2];
    // d_in[3] y_t, d_in[4] y_s, d_in[6] active_user: unused by reference
    const float* h0  = (const float*)d_in[5];
    const float* emb = (const float*)d_in[7];
    const float* Wih = (const float*)d_in[8];
    const float* Whh = (const float*)d_in[9];
    const float* bih = (const float*)d_in[10];
    const float* bhh = (const float*)d_in[11];
    const float* fcw = (const float*)d_in[12];
    const float* fcb = (const float*)d_in[13];
    float* out = (float*)d_out;

    static const int GRU_SMEM = (256 * 96 + 32 * ASH_STRIDE) * 4;
    cudaFuncSetAttribute(gru_persistent,
                         cudaFuncAttributeMaxDynamicSharedMemorySize, GRU_SMEM);

    // 1. transposes + fcw bf16 split + t/s relayout + barrier reset
    prep_kernel<<<(VV_ * HH_ + 255) / 256, 256>>>(Wih, Whh, fcw, t, s);

    // 2. P = emb @ Wih^T + bih  (2048x1536x512 — replaces entire gi GEMM)
    pgemm<<<dim3(H3_ / 128, VV_ / 128), 256>>>(emb, bih);

    // 3. GRU recurrence (gathers gi rows from L2-resident P)
    gru_persistent<<<GRU_BLOCKS, GRU_THREADS, GRU_SMEM>>>(h0, bhh, x);

    // 4. causal spatiotemporal weights + row sums
    wmat_kernel<<<dim3(SS_, UU_), 256>>>();

    // 5. out_w = (w @ out) / sum_w  -> bf16 hi/lo for fc
    attn_gemm<<<dim3(HH_ / 128, SS_ / 128, UU_), 256>>>();

    // 6. y = out_w @ fc_w^T + fc_b  (mma.sync split-bf16, preconverted fills)
    tgemm_fc<<<dim3(VV_ / 128, (SS_ * UU_) / 128), 256>>>(fcb, out);

    // 7. h_last
    hlast_kernel<<<(UU_ * HH_ + 255) / 256, 256>>>(out);
}